// round 12
// baseline (speedup 1.0000x reference)
#include <cuda_runtime.h>

#define NN 100000
#define NE 1200000
#define D 64
#define NL 3
#define NG 256
#define RH 128
#define RO 32
#define INDIM (D*NL)   // 192
#define MAXD 64        // padded neighbor-bucket capacity (Poisson(12): safe)

typedef unsigned long long ull;

// ---------------- scratch (device globals; no allocation allowed) ----------
__device__ int   d_deg[NN];
__device__ int   d_col2[NN * MAXD];   // padded adjacency buckets (25.6 MB)
__device__ float d_h0[NN * D];
__device__ float d_h1[NN * D];
__device__ float d_y[NN * D];
__device__ float d_g[NG * INDIM];

// ---------------- f32x2 helpers -------------------------------------------
static __device__ __forceinline__ void upk2(ull v, float& x, float& y) {
    asm("mov.b64 {%0, %1}, %2;" : "=f"(x), "=f"(y) : "l"(v));
}
static __device__ __forceinline__ void ffma2(ull& c, ull a, ull b) {
    asm("fma.rn.f32x2 %0, %1, %2, %0;" : "+l"(c) : "l"(a), "l"(b));
}

// ---------------- one-pass bucket CSR --------------------------------------
__global__ void k_scatter(const int* __restrict__ src, const int* __restrict__ dst) {
    int e = blockIdx.x * blockDim.x + threadIdx.x;
    if (e < NE) {
        int dn = dst[e];
        int p = atomicAdd(&d_deg[dn], 1);
        if (p < MAXD) d_col2[(dn << 6) + p] = src[e];
    }
}

// ---------------- zero readout accumulators (kernel, for ncu ordering) ----
__global__ void k_zerog() {
    int i = blockIdx.x * blockDim.x + threadIdx.x;
    if (i < NG * INDIM) d_g[i] = 0.0f;
}

// ---------------- dense GEMM: Y = Hin @ W[layer] ---------------------------
// 128-row x 64-col tile. Thread = 4 rows x 8 cols; acc k-parity packed f32x2.
// W pre-packed at staging so inner loop has zero repack MOVs.
// Per k-pair: 4 LDS.64 (z) + 4 LDS.128 (w) + 32 FFMA2.
__global__ void __launch_bounds__(256) k_gemm(
    const float* __restrict__ Hin, float* __restrict__ Y,
    const float* __restrict__ gin_W, int layer)
{
    __shared__ float Zs[128][66];                 // 33 KB, pad 2 (conflict-free)
    __shared__ __align__(16) uint4 Wp[32][32];    // [kpair][colpair] 16 KB

    int tid = threadIdx.x;
    int row0 = blockIdx.x * 128;

    // stage W pre-packed: Wp[kp][cp] = (W[2kp][2cp],W[2kp+1][2cp],
    //                                   W[2kp][2cp+1],W[2kp+1][2cp+1])
    const float* Wg = gin_W + layer * (D * D);
#pragma unroll
    for (int i = 0; i < 4; i++) {
        int e = tid + 256 * i;          // 0..1023
        int kp = e >> 5, cp = e & 31;
        uint4 v;
        v.x = __float_as_uint(Wg[(2 * kp)     * D + 2 * cp]);
        v.y = __float_as_uint(Wg[(2 * kp + 1) * D + 2 * cp]);
        v.z = __float_as_uint(Wg[(2 * kp)     * D + 2 * cp + 1]);
        v.w = __float_as_uint(Wg[(2 * kp + 1) * D + 2 * cp + 1]);
        Wp[kp][cp] = v;
    }

    // stage Z rows coalesced
    const float4* Hg = (const float4*)Hin;
#pragma unroll
    for (int i = 0; i < 8; i++) {
        int idx = tid + 256 * i;        // 0..2047
        int r = idx >> 4, c4 = idx & 15;
        int gr = row0 + r;
        int rc = (gr < NN) ? gr : (NN - 1);
        float4 v = Hg[(size_t)rc * 16 + c4];
        float2* p = (float2*)&Zs[r][c4 * 4];
        p[0] = make_float2(v.x, v.y);
        p[1] = make_float2(v.z, v.w);
    }
    __syncthreads();

    int cg = tid & 7;                   // col group: cols cg*8..cg*8+7
    int rgid = tid >> 3;                // 0..31: rows rgid*4..rgid*4+3

    ull acc[4][8];
#pragma unroll
    for (int i = 0; i < 4; i++)
#pragma unroll
        for (int c = 0; c < 8; c++) acc[i][c] = 0ull;

#pragma unroll 4
    for (int kp = 0; kp < 32; kp++) {
        ulonglong2 wv[4];
        const ulonglong2* wrow = (const ulonglong2*)&Wp[kp][cg * 4];
#pragma unroll
        for (int j = 0; j < 4; j++) wv[j] = wrow[j];   // LDS.128 broadcast
        ull z[4];
#pragma unroll
        for (int i = 0; i < 4; i++)
            z[i] = *(const ull*)&Zs[rgid * 4 + i][2 * kp];
#pragma unroll
        for (int i = 0; i < 4; i++) {
#pragma unroll
            for (int j = 0; j < 4; j++) {
                ffma2(acc[i][2 * j],     wv[j].x, z[i]);
                ffma2(acc[i][2 * j + 1], wv[j].y, z[i]);
            }
        }
    }

    // epilogue: out[c] = even-k partial + odd-k partial; 2x STG.128 per row
#pragma unroll
    for (int i = 0; i < 4; i++) {
        int gr = row0 + rgid * 4 + i;
        if (gr < NN) {
            float lo, hi;
            float4 o0, o1;
            upk2(acc[i][0], lo, hi); o0.x = lo + hi;
            upk2(acc[i][1], lo, hi); o0.y = lo + hi;
            upk2(acc[i][2], lo, hi); o0.z = lo + hi;
            upk2(acc[i][3], lo, hi); o0.w = lo + hi;
            upk2(acc[i][4], lo, hi); o1.x = lo + hi;
            upk2(acc[i][5], lo, hi); o1.y = lo + hi;
            upk2(acc[i][6], lo, hi); o1.z = lo + hi;
            upk2(acc[i][7], lo, hi); o1.w = lo + hi;
            float4* yr = (float4*)(Y + (size_t)gr * D + cg * 8);
            yr[0] = o0; yr[1] = o1;
        }
    }
}

// ---------------- fused aggregation + per-graph readout -------------------
__global__ void __launch_bounds__(256) k_agg(
    const float* __restrict__ Y, float* __restrict__ hout,
    const float* __restrict__ gin_b, const float* __restrict__ eps,
    const int* __restrict__ gids, int layer)
{
    __shared__ float2 sm[8][32];
    __shared__ int sg[8];

    int tid = threadIdx.x;
    int w = tid >> 5;
    int lane = tid & 31;
    int node = blockIdx.x * 8 + w;   // NN % 8 == 0

    float epsv = 1.0f + eps[layer];
    float2 b2 = ((const float2*)(gin_b + layer * D))[lane];

    float2 acc = ((const float2*)(Y + (size_t)node * D))[lane];
    acc.x *= epsv; acc.y *= epsv;

    int deg = d_deg[node];
    int beg = node << 6;
    int end = beg + deg;
    for (int e0 = beg; e0 < end; e0 += 32) {
        int idx = e0 + lane;
        int sn = (idx < end) ? d_col2[idx] : 0;
        int cnt = min(32, end - e0);
        int j = 0;
        for (; j + 4 <= cnt; j += 4) {
            int s0 = __shfl_sync(0xffffffffu, sn, j + 0);
            int s1 = __shfl_sync(0xffffffffu, sn, j + 1);
            int s2 = __shfl_sync(0xffffffffu, sn, j + 2);
            int s3 = __shfl_sync(0xffffffffu, sn, j + 3);
            float2 v0 = ((const float2*)(Y + (size_t)s0 * D))[lane];
            float2 v1 = ((const float2*)(Y + (size_t)s1 * D))[lane];
            float2 v2 = ((const float2*)(Y + (size_t)s2 * D))[lane];
            float2 v3 = ((const float2*)(Y + (size_t)s3 * D))[lane];
            acc.x += v0.x + v1.x + v2.x + v3.x;
            acc.y += v0.y + v1.y + v2.y + v3.y;
        }
        for (; j < cnt; j++) {
            int sj = __shfl_sync(0xffffffffu, sn, j);
            float2 v = ((const float2*)(Y + (size_t)sj * D))[lane];
            acc.x += v.x; acc.y += v.y;
        }
    }

    float2 o;
    o.x = fmaxf(acc.x + b2.x, 0.0f);
    o.y = fmaxf(acc.y + b2.y, 0.0f);
    ((float2*)(hout + (size_t)node * D))[lane] = o;

    // epilogue: per-graph segment reduce of this block's 8 rows
    sm[w][lane] = o;
    if (lane == 0) sg[w] = gids[node];
    __syncthreads();

    if (tid < D) {
        int dd = tid;
        int pair = dd >> 1;
        int comp = dd & 1;
        float run = 0.0f;
        int curg = sg[0];
#pragma unroll
        for (int n = 0; n < 8; n++) {
            int gn = sg[n];
            float2 v2 = sm[n][pair];
            float v = comp ? v2.y : v2.x;
            if (gn != curg) {
                atomicAdd(&d_g[curg * INDIM + layer * D + dd], run);
                run = 0.0f;
                curg = gn;
            }
            run += v;
        }
        atomicAdd(&d_g[curg * INDIM + layer * D + dd], run);
    }
}

// ---------------- readout MLP ---------------------------------------------
__global__ void k_mlp(const float* __restrict__ W1, const float* __restrict__ b1,
                      const float* __restrict__ W2, const float* __restrict__ b2,
                      float* __restrict__ out)
{
    __shared__ float gv[INDIM];
    __shared__ float hid[RH];
    int b = blockIdx.x;
    int tid = threadIdx.x;   // 128 threads
    for (int i = tid; i < INDIM; i += RH) gv[i] = d_g[b * INDIM + i];
    __syncthreads();
    float a = b1[tid];
#pragma unroll 8
    for (int k = 0; k < INDIM; k++)
        a += gv[k] * W1[k * RH + tid];
    hid[tid] = fmaxf(a, 0.0f);
    __syncthreads();
    if (tid < RO) {
        float o = b2[tid];
#pragma unroll 8
        for (int k = 0; k < RH; k++)
            o += hid[k] * W2[k * RO + tid];
        out[b * RO + tid] = o;
    }
}

// ---------------- launch ---------------------------------------------------
extern "C" void kernel_launch(void* const* d_in, const int* in_sizes, int n_in,
                              void* d_out, int out_size)
{
    const float* x      = (const float*)d_in[0];
    const float* gin_W  = (const float*)d_in[1];
    const float* gin_b  = (const float*)d_in[2];
    const float* eps    = (const float*)d_in[3];
    const float* r_W1   = (const float*)d_in[4];
    const float* r_b1   = (const float*)d_in[5];
    const float* r_W2   = (const float*)d_in[6];
    const float* r_b2   = (const float*)d_in[7];
    const int*   src    = (const int*)d_in[8];
    const int*   dst    = (const int*)d_in[9];
    const int*   gids   = (const int*)d_in[10];
    float* out = (float*)d_out;

    static float* h0p = nullptr;
    static float* h1p = nullptr;
    static float* yp  = nullptr;
    static int*   degp = nullptr;
    if (!h0p) {
        cudaGetSymbolAddress((void**)&h0p, d_h0);
        cudaGetSymbolAddress((void**)&h1p, d_h1);
        cudaGetSymbolAddress((void**)&yp,  d_y);
        cudaGetSymbolAddress((void**)&degp, d_deg);
    }

    cudaMemsetAsync(degp, 0, NN * sizeof(int));
    // kernel launch sequence: scatter(0), zerog(1), gemm0(2), agg0(3),
    // gemm1(4), agg1(5) <- ncu -s 5 captures an agg next round
    k_scatter<<<(NE + 255) / 256, 256>>>(src, dst);
    k_zerog<<<(NG * INDIM + 255) / 256, 256>>>();

    const float* hin = x;
    float* bufs[2] = { h0p, h1p };
    for (int l = 0; l < NL; l++) {
        float* hout = bufs[l & 1];
        k_gemm<<<(NN + 127) / 128, 256>>>(hin, yp, gin_W, l);
        k_agg<<<NN / 8, 256>>>(yp, hout, gin_b, eps, gids, l);
        hin = hout;
    }

    k_mlp<<<NG, RH>>>(r_W1, r_b1, r_W2, r_b2, out);
}

// round 15
// speedup vs baseline: 1.3789x; 1.3789x over previous
#include <cuda_runtime.h>

#define NN 100000
#define NE 1200000
#define D 64
#define NL 3
#define NG 256
#define RH 128
#define RO 32
#define INDIM (D*NL)   // 192
#define GR 64          // rows per GEMM block
#define MAXD 64        // padded neighbor-bucket capacity (Poisson(12): safe)

typedef unsigned long long ull;

// ---------------- scratch (device globals; no allocation allowed) ----------
__device__ int   d_deg[NN];
__device__ int   d_col2[NN * MAXD];   // padded adjacency buckets (25.6 MB)
__device__ float d_h0[NN * D];
__device__ float d_h1[NN * D];
__device__ float d_y[NN * D];
__device__ float d_g[NG * INDIM];

// ---------------- f32x2 helpers -------------------------------------------
static __device__ __forceinline__ ull pk2(float x, float y) {
    ull r; asm("mov.b64 %0, {%1, %2};" : "=l"(r) : "f"(x), "f"(y)); return r;
}
static __device__ __forceinline__ void upk2(ull v, float& x, float& y) {
    asm("mov.b64 {%0, %1}, %2;" : "=f"(x), "=f"(y) : "l"(v));
}
static __device__ __forceinline__ void ffma2(ull& c, ull a, ull b) {
    asm("fma.rn.f32x2 %0, %1, %2, %0;" : "+l"(c) : "l"(a), "l"(b));
}

// ---------------- one-pass bucket CSR --------------------------------------
__global__ void k_scatter(const int* __restrict__ src, const int* __restrict__ dst) {
    int e = blockIdx.x * blockDim.x + threadIdx.x;
    if (e < NE) {
        int dn = dst[e];
        int p = atomicAdd(&d_deg[dn], 1);
        if (p < MAXD) d_col2[(dn << 6) + p] = src[e];
    }
}

__global__ void k_zerog() {
    int i = blockIdx.x * blockDim.x + threadIdx.x;
    if (i < NG * INDIM) d_g[i] = 0.0f;
}

// ---------------- dense GEMM: Y = Hin @ W[layer] (R11 measured-best) -------
__global__ void __launch_bounds__(256) k_gemm(
    const float* __restrict__ Hin, float* __restrict__ Y,
    const float* __restrict__ gin_W, int layer)
{
    __shared__ float4 Zs[GR][16];     // 64 rows x 64 floats (16 KB)
    __shared__ float2 Wsp[D][32];     // W[k][dp] pairs (16 KB)

    int tid = threadIdx.x;
    int row0 = blockIdx.x * GR;

    const float4* Wg = (const float4*)(gin_W + layer * D * D);
    float4* Ws4 = (float4*)&Wsp[0][0];
#pragma unroll
    for (int i = 0; i < 4; i++) Ws4[tid + 256 * i] = Wg[tid + 256 * i];

    const float4* Hg = (const float4*)Hin;
#pragma unroll
    for (int i = 0; i < 4; i++) {
        int idx = tid + 256 * i;
        int r = row0 + (idx >> 4);
        int rc = (r < NN) ? r : (NN - 1);
        Zs[idx >> 4][idx & 15] = Hg[(size_t)rc * 16 + (idx & 15)];
    }
    __syncthreads();

    int dp = tid & 31;
    int rg = tid >> 5;

    ull accA[8], accB[8];
#pragma unroll
    for (int n = 0; n < 8; n++) { accA[n] = 0ull; accB[n] = 0ull; }

    for (int kc = 0; kc < D; kc += 16) {
        ull wA[8], wB[8];
#pragma unroll
        for (int p = 0; p < 8; p++) {
            float2 lo = Wsp[kc + 2 * p][dp];
            float2 hi = Wsp[kc + 2 * p + 1][dp];
            wA[p] = pk2(lo.x, hi.x);
            wB[p] = pk2(lo.y, hi.y);
        }
#pragma unroll
        for (int n = 0; n < 8; n++) {
            const ull* zrowU = (const ull*)&Zs[rg * 8 + n][0];
#pragma unroll
            for (int q = 0; q < 4; q++) {
                ull zA = zrowU[kc / 2 + 2 * q];
                ull zB = zrowU[kc / 2 + 2 * q + 1];
                ffma2(accA[n], wA[2 * q],     zA);
                ffma2(accB[n], wB[2 * q],     zA);
                ffma2(accA[n], wA[2 * q + 1], zB);
                ffma2(accB[n], wB[2 * q + 1], zB);
            }
        }
    }

#pragma unroll
    for (int n = 0; n < 8; n++) {
        int r = row0 + rg * 8 + n;
        if (r < NN) {
            float ax, ay, bx, by;
            upk2(accA[n], ax, ay);
            upk2(accB[n], bx, by);
            ((float2*)(Y + (size_t)r * D))[dp] = make_float2(ax + ay, bx + by);
        }
    }
}

// ---------------- fused aggregation + per-graph readout -------------------
// 16 lanes per node (2 nodes/warp), float4 per lane. Warp-uniform loop bound
// (max of the two nodes' degrees) keeps all lanes converged for shfl; loads
// predicated per half-warp.
__global__ void __launch_bounds__(256) k_agg(
    const float* __restrict__ Y, float* __restrict__ hout,
    const float* __restrict__ gin_b, const float* __restrict__ eps,
    const int* __restrict__ gids, int layer)
{
    __shared__ float sm[16][D];
    __shared__ int sg[16];

    int tid = threadIdx.x;
    int lane = tid & 31;
    int gl = lane & 15;              // lane within 16-group
    int base = lane & 16;            // 0 for low half, 16 for high half
    int grp = tid >> 4;              // 0..15: node group within block
    int node = blockIdx.x * 16 + grp;   // NN % 16 == 0

    float epsv = 1.0f + eps[layer];
    const float4* b4 = (const float4*)(gin_b + layer * D);
    float4 bv = b4[gl];

    const float4* yrow = (const float4*)(Y + (size_t)node * D);
    float4 acc = yrow[gl];
    acc.x *= epsv; acc.y *= epsv; acc.z *= epsv; acc.w *= epsv;

    int deg = min(d_deg[node], MAXD);
    int degMax = max(deg, __shfl_xor_sync(0xffffffffu, deg, 16));

    // whole bucket: 64 ints = 16 lanes x int4, one coalesced load
    int4 iv = ((const int4*)&d_col2[node << 6])[gl];

    for (int j4 = 0; j4 < degMax; j4 += 4) {
        int slot = base + (j4 >> 2);
        int s0 = __shfl_sync(0xffffffffu, iv.x, slot);
        int s1 = __shfl_sync(0xffffffffu, iv.y, slot);
        int s2 = __shfl_sync(0xffffffffu, iv.z, slot);
        int s3 = __shfl_sync(0xffffffffu, iv.w, slot);
        int rem = deg - j4;          // may be <= 0 for this half-warp
        if (rem >= 4) {
            float4 v0 = ((const float4*)(Y + (size_t)s0 * D))[gl];
            float4 v1 = ((const float4*)(Y + (size_t)s1 * D))[gl];
            float4 v2 = ((const float4*)(Y + (size_t)s2 * D))[gl];
            float4 v3 = ((const float4*)(Y + (size_t)s3 * D))[gl];
            acc.x += (v0.x + v1.x) + (v2.x + v3.x);
            acc.y += (v0.y + v1.y) + (v2.y + v3.y);
            acc.z += (v0.z + v1.z) + (v2.z + v3.z);
            acc.w += (v0.w + v1.w) + (v2.w + v3.w);
        } else if (rem > 0) {
            {
                float4 v = ((const float4*)(Y + (size_t)s0 * D))[gl];
                acc.x += v.x; acc.y += v.y; acc.z += v.z; acc.w += v.w;
            }
            if (rem > 1) {
                float4 v = ((const float4*)(Y + (size_t)s1 * D))[gl];
                acc.x += v.x; acc.y += v.y; acc.z += v.z; acc.w += v.w;
            }
            if (rem > 2) {
                float4 v = ((const float4*)(Y + (size_t)s2 * D))[gl];
                acc.x += v.x; acc.y += v.y; acc.z += v.z; acc.w += v.w;
            }
        }
    }

    float4 o;
    o.x = fmaxf(acc.x + bv.x, 0.0f);
    o.y = fmaxf(acc.y + bv.y, 0.0f);
    o.z = fmaxf(acc.z + bv.z, 0.0f);
    o.w = fmaxf(acc.w + bv.w, 0.0f);
    ((float4*)(hout + (size_t)node * D))[gl] = o;

    // epilogue: per-graph segment reduce of this block's 16 rows
    ((float4*)&sm[grp][0])[gl] = o;
    if (gl == 0) sg[grp] = gids[node];
    __syncthreads();

    if (tid < D) {
        int dd = tid;
        float run = 0.0f;
        int curg = sg[0];
#pragma unroll
        for (int n = 0; n < 16; n++) {
            int gn = sg[n];
            float v = sm[n][dd];
            if (gn != curg) {
                atomicAdd(&d_g[curg * INDIM + layer * D + dd], run);
                run = 0.0f;
                curg = gn;
            }
            run += v;
        }
        atomicAdd(&d_g[curg * INDIM + layer * D + dd], run);
    }
}

// ---------------- readout MLP ---------------------------------------------
__global__ void k_mlp(const float* __restrict__ W1, const float* __restrict__ b1,
                      const float* __restrict__ W2, const float* __restrict__ b2,
                      float* __restrict__ out)
{
    __shared__ float gv[INDIM];
    __shared__ float hid[RH];
    int b = blockIdx.x;
    int tid = threadIdx.x;   // 128 threads
    for (int i = tid; i < INDIM; i += RH) gv[i] = d_g[b * INDIM + i];
    __syncthreads();
    float a = b1[tid];
#pragma unroll 8
    for (int k = 0; k < INDIM; k++)
        a += gv[k] * W1[k * RH + tid];
    hid[tid] = fmaxf(a, 0.0f);
    __syncthreads();
    if (tid < RO) {
        float o = b2[tid];
#pragma unroll 8
        for (int k = 0; k < RH; k++)
            o += hid[k] * W2[k * RO + tid];
        out[b * RO + tid] = o;
    }
}

// ---------------- launch ---------------------------------------------------
extern "C" void kernel_launch(void* const* d_in, const int* in_sizes, int n_in,
                              void* d_out, int out_size)
{
    const float* x      = (const float*)d_in[0];
    const float* gin_W  = (const float*)d_in[1];
    const float* gin_b  = (const float*)d_in[2];
    const float* eps    = (const float*)d_in[3];
    const float* r_W1   = (const float*)d_in[4];
    const float* r_b1   = (const float*)d_in[5];
    const float* r_W2   = (const float*)d_in[6];
    const float* r_b2   = (const float*)d_in[7];
    const int*   src    = (const int*)d_in[8];
    const int*   dst    = (const int*)d_in[9];
    const int*   gids   = (const int*)d_in[10];
    float* out = (float*)d_out;

    static float* h0p = nullptr;
    static float* h1p = nullptr;
    static float* yp  = nullptr;
    static int*   degp = nullptr;
    if (!h0p) {
        cudaGetSymbolAddress((void**)&h0p, d_h0);
        cudaGetSymbolAddress((void**)&h1p, d_h1);
        cudaGetSymbolAddress((void**)&yp,  d_y);
        cudaGetSymbolAddress((void**)&degp, d_deg);
    }

    cudaMemsetAsync(degp, 0, NN * sizeof(int));
    k_scatter<<<(NE + 255) / 256, 256>>>(src, dst);
    k_zerog<<<(NG * INDIM + 255) / 256, 256>>>();

    const float* hin = x;
    float* bufs[2] = { h0p, h1p };
    for (int l = 0; l < NL; l++) {
        float* hout = bufs[l & 1];
        k_gemm<<<(NN + GR - 1) / GR, 256>>>(hin, yp, gin_W, l);
        k_agg<<<NN / 16, 256>>>(yp, hout, gin_b, eps, gids, l);
        hin = hout;
    }

    k_mlp<<<NG, RH>>>(r_W1, r_b1, r_W2, r_b2, out);
}